// round 4
// baseline (speedup 1.0000x reference)
#include <cuda_runtime.h>

// Problem constants
#define DD  48
#define HH  256
#define WW  256
#define DM  48
#define HM  128
#define WM  128
#define PHN 4

// image:  d_in[0]  float32 [1][1][48][256][256][2]  = 6,291,456
// mvf:    d_in[1]  float32 [1][4][3][48][128][128]  = 9,437,184
// out:             float32 [1][5][48][256][256][2]  = 31,457,280

#define COPY_N4  (DD * HH * WW * 2 / 4)   // 1,572,864 float4 (phase-0 copy)
#define WARP_N   (PHN * DD * HH * WW)     // 12,582,912 output pixels (1 px/thread)

__global__ __launch_bounds__(256) void mvf_fused_kernel(
    const float* __restrict__ image,   // [48][256][256][2]
    const float* __restrict__ mvf,     // [4][3][48][128][128]
    float4* __restrict__ out4)         // [5][48][256][256][2] viewed as float4
{
    int tid = blockIdx.x * blockDim.x + threadIdx.x;

    // ---- First COPY_N4 threads: stream phase-0 (identity copy) ----
    if (tid < COPY_N4) {
        out4[tid] = ((const float4*)image)[tid];
        return;
    }
    tid -= COPY_N4;
    if (tid >= WARP_N) return;

    // 1 output pixel per thread; warp spans 32 consecutive x (256B) for
    // minimal line-span per gather instruction.
    const int x  = tid & 255;
    const int y  = (tid >> 8) & 255;
    const int zp = tid >> 16;          // p*48 + z  in [0,192)
    const int p  = zp / DD;
    const int z  = zp - p * DD;

    // --- upsample source coords (align_corners trilinear, D identity) ---
    float ux = fminf(fmaxf(0.5f * (float)x - 0.25f, 0.0f), (float)(WM - 1));
    float uy = fminf(fmaxf(0.5f * (float)y - 0.25f, 0.0f), (float)(HM - 1));
    const int   jx  = (int)ux;
    const int   jy  = (int)uy;
    const float fx  = ux - (float)jx;
    const float fy  = uy - (float)jy;
    const int   jx1 = min(jx + 1, WM - 1);
    const int   jy1 = min(jy + 1, HM - 1);

    // --- bilinear-upsample the 3 flow components ---
    const float* __restrict__ mbase = mvf + (((p * 3) * DM + z) << 14); // *128*128
    float flow[3];
    #pragma unroll
    for (int c = 0; c < 3; ++c) {
        const float* __restrict__ m = mbase + ((c * DM) << 14);
        const float v00 = __ldg(&m[(jy  << 7) + jx ]);
        const float v01 = __ldg(&m[(jy  << 7) + jx1]);
        const float v10 = __ldg(&m[(jy1 << 7) + jx ]);
        const float v11 = __ldg(&m[(jy1 << 7) + jx1]);
        const float t0 = fmaf(fx, v01 - v00, v00);
        const float t1 = fmaf(fx, v11 - v10, v10);
        flow[c] = fmaf(fy, t1 - t0, t0);
    }

    // --- absolute sample coordinates (flow scaled by (1,2,2)) ---
    const float cz = (float)z + flow[0];
    const float cy = (float)y + 2.0f * flow[1];
    const float cx = (float)x + 2.0f * flow[2];

    const float fz0 = floorf(cz);
    const float fy0 = floorf(cy);
    const float fx0 = floorf(cx);
    const int z0 = (int)fz0;
    const int y0 = (int)fy0;
    const int x0 = (int)fx0;
    const float wz = cz - fz0;
    const float wy = cy - fy0;
    const float wx = cx - fx0;

    // --- trilinear gather with zeros padding (branchless) ---
    const float2* __restrict__ img2 = (const float2*)image;
    float accx = 0.0f, accy = 0.0f;
    #pragma unroll
    for (int dz = 0; dz < 2; ++dz) {
        const int zi = z0 + dz;
        const float wzt = dz ? wz : (1.0f - wz);
        const int zc = min(max(zi, 0), DD - 1);
        #pragma unroll
        for (int dy = 0; dy < 2; ++dy) {
            const int yi = y0 + dy;
            const float wyt = dy ? wy : (1.0f - wy);
            const int yc = min(max(yi, 0), HH - 1);
            const int rowbase = (zc * HH + yc) * WW;
            const float wzy = wzt * wyt;
            #pragma unroll
            for (int dx = 0; dx < 2; ++dx) {
                const int xi = x0 + dx;
                const float wxt = dx ? wx : (1.0f - wx);
                const int xc = min(max(xi, 0), WW - 1);
                const bool valid = ((unsigned)zi < DD) & ((unsigned)yi < HH) & ((unsigned)xi < WW);
                float w = wzy * wxt;
                w = valid ? w : 0.0f;
                const float2 v = __ldg(&img2[rowbase + xc]);
                accx = fmaf(w, v.x, accx);
                accy = fmaf(w, v.y, accy);
            }
        }
    }

    // Output float2 index for phase p+1 = COPY_N4*2 + tid
    float2 res;
    res.x = accx;
    res.y = accy;
    ((float2*)out4)[COPY_N4 * 2 + tid] = res;
}

extern "C" void kernel_launch(void* const* d_in, const int* in_sizes, int n_in,
                              void* d_out, int out_size)
{
    const float* image = (const float*)d_in[0];
    const float* mvf   = (const float*)d_in[1];

    const int total = COPY_N4 + WARP_N;   // 14,155,776 threads = 55,296 blocks
    mvf_fused_kernel<<<(total + 255) / 256, 256>>>(image, mvf, (float4*)d_out);
}